// round 15
// baseline (speedup 1.0000x reference)
#include <cuda_runtime.h>
#include <cuda_fp16.h>
#include <math.h>

// ---------------- problem constants ----------------
#define BB    4
#define CDIM  96
#define LL    4096      // 64*64
#define DI    192
#define DS    16
#define RNK   6
#define NDIR  16        // 4 directions * BB
#define CT    64        // chunk length
#define NC    64        // number of chunks

// ---------------- scratch (device globals; no allocation) ----------------
__device__ float  g_xn[BB * LL * CDIM];             // [b][p][c]
__device__ float  g_gateT[(size_t)NDIR * LL];       // [n][l]
__device__ __half g_xsh[(size_t)BB * LL * DI];      // [b][p][d]  xs fp16
__device__ float  g_zs[(size_t)BB * LL * DI];       // [b][p][d]  silu(z) fp32
__device__ float  g_dtm[(size_t)NDIR * LL * RNK];   // [n][l][r]
__device__ float  g_BC[(size_t)NDIR * LL * 32];     // [n][l][B0..15,C0..15]
__device__ float  g_ycomb[(size_t)BB * LL * DI];    // [b][p][d]
__device__ float  g_H[(size_t)NDIR * NC * DI * DS]; // [n][c][d][s]
__device__ float  g_P[(size_t)NDIR * NC * DI * DS]; // [n][c][d][s]
__device__ __half g_Wh1[48 * 192];                  // x_proj_w fp16 (padded 48 rows)
__device__ __half g_Wh2[96 * 192];                  // out_proj_w fp16
__device__ __half g_Whin[384 * 96];                 // in_proj_w fp16

__device__ __forceinline__ int pmap(int l, int k) {
    int lr = (k & 2) ? (LL - 1 - l) : l;
    return (k & 1) ? (((lr & 63) << 6) | (lr >> 6)) : lr;
}

__device__ __forceinline__ float ex2(float x) {
    float y;
    asm("ex2.approx.f32 %0, %1;" : "=f"(y) : "f"(x));
    return y;
}

__device__ __forceinline__ void mma16816(float* d, const unsigned* a, const unsigned* b) {
    asm volatile("mma.sync.aligned.m16n8k16.row.col.f32.f16.f16.f32 "
        "{%0,%1,%2,%3}, {%4,%5,%6,%7}, {%8,%9}, {%0,%1,%2,%3};"
        : "+f"(d[0]), "+f"(d[1]), "+f"(d[2]), "+f"(d[3])
        : "r"(a[0]), "r"(a[1]), "r"(a[2]), "r"(a[3]), "r"(b[0]), "r"(b[1]));
}
__device__ __forceinline__ float silu(float v) { return v / (1.f + __expf(-v)); }
__device__ __forceinline__ float softplus_f(float s) {
    return (s > 20.f) ? s : __logf(1.f + __expf(s));
}

// ---------------- K1: layernorm + gate MLP (+ zero ycomb, gateT, weight prep) ----------------
__global__ void __launch_bounds__(128) norm_gate_kernel(
    const float* __restrict__ x, const float* __restrict__ ng, const float* __restrict__ nb,
    const float* __restrict__ w1, const float* __restrict__ b1,
    const float* __restrict__ w2, const float* __restrict__ b2,
    const float* __restrict__ xw, const float* __restrict__ ow, const float* __restrict__ iw)
{
    __shared__ float xs_s[CDIM][33];
    __shared__ float w1_s[24 * 96];
    const int tid = threadIdx.x;
    const int P0 = blockIdx.x * 32;
    const int b = P0 >> 12, p0 = P0 & 4095;

    // folded weight prep: 64512 fp16 conversions spread over 512 blocks
    {
        int i = blockIdx.x * 126 + tid;
        if (tid < 126 && i < 64512) {
            if (i < 9216)        g_Wh1[i] = __float2half(i < 38 * 192 ? xw[i] : 0.f);
            else if (i < 27648)  g_Wh2[i - 9216] = __float2half(ow[i - 9216]);
            else                 g_Whin[i - 27648] = __float2half(iw[i - 27648]);
        }
    }
    {
        size_t base = (size_t)blockIdx.x * 6144;
        for (int i = tid; i < 6144; i += 128) g_ycomb[base + i] = 0.f;
    }
    for (int i = tid; i < 96 * 32; i += 128) {
        int c = i >> 5, pi = i & 31;
        xs_s[c][pi] = x[((size_t)b * 96 + c) * 4096 + p0 + pi];
    }
    for (int i = tid; i < 24 * 96; i += 128) w1_s[i] = w1[i];
    __syncthreads();

    if (tid < 32) {
        const int lane = tid;
        float mu = 0.f;
        #pragma unroll
        for (int c = 0; c < 96; c++) mu += xs_s[c][lane];
        mu *= (1.f / 96.f);
        float var = 0.f;
        #pragma unroll
        for (int c = 0; c < 96; c++) { float dv = xs_s[c][lane] - mu; var += dv * dv; }
        var *= (1.f / 96.f);
        const float inv = rsqrtf(var + 1e-5f);
        #pragma unroll
        for (int c = 0; c < 96; c++)
            xs_s[c][lane] = (xs_s[c][lane] - mu) * inv * ng[c] + nb[c];

        float hbuf[24];
        #pragma unroll 4
        for (int jj = 0; jj < 24; jj++) {
            float s = b1[jj];
            for (int c = 0; c < 96; c++) s += xs_s[c][lane] * w1_s[jj * 96 + c];
            hbuf[jj] = tanhf(s);
        }
        float lg[4];
        #pragma unroll
        for (int q = 0; q < 4; q++) {
            float s = b2[q];
            #pragma unroll
            for (int jj = 0; jj < 24; jj++) s += hbuf[jj] * w2[q * 24 + jj];
            lg[q] = s;
        }
        float m = fmaxf(fmaxf(lg[0], lg[1]), fmaxf(lg[2], lg[3]));
        float e[4], se = 0.f;
        #pragma unroll
        for (int q = 0; q < 4; q++) { e[q] = __expf(lg[q] - m); se += e[q]; }
        float rs = 1.f / se;
        const int p = p0 + lane;
        #pragma unroll
        for (int q = 0; q < 4; q++) {
            int l = pmap(p, q);
            g_gateT[(size_t)(q * 4 + b) * LL + l] = e[q] * rs;
        }
    }
    __syncthreads();
    for (int i = tid; i < 32 * 96; i += 128) {
        int pi = i / 96, c = i % 96;
        g_xn[(size_t)(b * 4096 + p0 + pi) * 96 + c] = xs_s[c][pi];
    }
}

// ---------------- in_proj via tensor cores ----------------
__global__ void __launch_bounds__(256) inproj_mma()
{
    __shared__ __half sA[64][104];
    const int tid = threadIdx.x;
    const int w = tid >> 5, lane = tid & 31;
    const int m0 = blockIdx.x * 64;

    for (int i = tid; i < 64 * 24; i += 256) {
        int m = i / 24, kq = (i - m * 24) * 4;
        float4 v = *(const float4*)&g_xn[(size_t)(m0 + m) * 96 + kq];
        *(__half2*)&sA[m][kq]     = __floats2half2_rn(v.x, v.y);
        *(__half2*)&sA[m][kq + 2] = __floats2half2_rn(v.z, v.w);
    }
    __syncthreads();

    const int qr = lane >> 2, qc = (lane & 3) << 1;
    const int wt = w & 3, nh = (w >> 2) * 192;
    const int rA = wt * 16 + qr;

    float acc[24][4];
    #pragma unroll
    for (int g = 0; g < 24; g++)
        #pragma unroll
        for (int q = 0; q < 4; q++) acc[g][q] = 0.f;

    #pragma unroll
    for (int ks = 0; ks < 6; ks++) {
        const int k = ks * 16 + qc;
        unsigned a[4];
        a[0] = *(const unsigned*)&sA[rA][k];
        a[1] = *(const unsigned*)&sA[rA + 8][k];
        a[2] = *(const unsigned*)&sA[rA][k + 8];
        a[3] = *(const unsigned*)&sA[rA + 8][k + 8];
        #pragma unroll
        for (int g = 0; g < 24; g++) {
            int n = nh + g * 8 + qr;
            unsigned bf[2];
            bf[0] = *(const unsigned*)&g_Whin[n * 96 + k];
            bf[1] = *(const unsigned*)&g_Whin[n * 96 + k + 8];
            mma16816(acc[g], a, bf);
        }
    }

    const int t0 = m0 + wt * 16 + qr;
    #pragma unroll
    for (int g = 0; g < 24; g++) {
        int cn = nh + g * 8 + qc;
        if (nh == 0) {
            *(__half2*)&g_xsh[(size_t)t0 * DI + cn]       = __floats2half2_rn(acc[g][0], acc[g][1]);
            *(__half2*)&g_xsh[(size_t)(t0 + 8) * DI + cn] = __floats2half2_rn(acc[g][2], acc[g][3]);
        } else {
            int zc = cn - 192;
            *(float2*)&g_zs[(size_t)t0 * DI + zc]       = make_float2(silu(acc[g][0]), silu(acc[g][1]));
            *(float2*)&g_zs[(size_t)(t0 + 8) * DI + zc] = make_float2(silu(acc[g][2]), silu(acc[g][3]));
        }
    }
}

// ---------------- x_proj via tensor cores (conv fused, smem-staged B operand) ----------------
// dynamic smem: sW[48*200] | sXs[67*200] | sX[64*200]   (71600 B)
__global__ void __launch_bounds__(128) xproj_mma(
    const float* __restrict__ cw, const float* __restrict__ cb)
{
    extern __shared__ __half xsm[];
    __half* sW  = xsm;            // [48][200]
    __half* sXs = xsm + 9600;     // [67][200]  raw xs pixels (halo 3)
    __half* sX  = xsm + 23000;    // [64][200]  conv output, token-major
    __shared__ float scw[DI][4];
    __shared__ float scb[DI];

    const int tid = threadIdx.x;
    const int w = tid >> 5, lane = tid & 31;
    const int m0 = blockIdx.x * 64;
    const int nd = m0 >> 12, l0 = m0 & 4095;
    const int b = nd & 3, k = nd >> 2;

    for (int i = tid; i < 48 * 192; i += 128) {
        int r = i / 192, c = i - r * 192;
        sW[r * 200 + c] = g_Wh1[i];
    }
    for (int i = tid; i < DI * 4; i += 128) scw[i >> 2][i & 3] = cw[i];
    for (int i = tid; i < DI; i += 128) scb[i] = cb[i];   // FIX: full 192 extent
    // stage raw xs pixels: rows = pixel idx (scan pos l0-3+idx), cols = d
    for (int i = tid; i < 67 * 96; i += 128) {
        int idx = i / 96, d2 = (i - idx * 96) << 1;
        int pix = l0 - 3 + idx;
        __half2 v = (pix >= 0)
            ? *(const __half2*)&g_xsh[((size_t)b * LL + pmap(pix, k)) * DI + d2]
            : __floats2half2_rn(0.f, 0.f);
        *(__half2*)&sXs[idx * 200 + d2] = v;
    }
    __syncthreads();

    // conv + silu -> sX[t][d]
    for (int i = tid; i < 64 * 96; i += 128) {
        int t = i / 96, dp = (i - t * 96) << 1;
        float u0 = scb[dp], u1 = scb[dp + 1];
        #pragma unroll
        for (int tap = 0; tap < 4; tap++) {
            float2 xv = __half22float2(*(const __half2*)&sXs[(t + tap) * 200 + dp]);
            u0 += scw[dp][tap] * xv.x;
            u1 += scw[dp + 1][tap] * xv.y;
        }
        *(__half2*)&sX[t * 200 + dp] = __floats2half2_rn(silu(u0), silu(u1));
    }
    __syncthreads();

    const int qr = lane >> 2, qc = (lane & 3) << 1;
    const int tloc = w * 16 + qr;

    float acc[3][2][4];
    #pragma unroll
    for (int g = 0; g < 3; g++)
        #pragma unroll
        for (int t = 0; t < 2; t++)
            #pragma unroll
            for (int q = 0; q < 4; q++) acc[g][t][q] = 0.f;

    #pragma unroll 2
    for (int ks = 0; ks < 12; ks++) {
        const int kk = ks * 16 + qc;
        unsigned a[3][4];
        #pragma unroll
        for (int g = 0; g < 3; g++) {
            int r = g * 16 + qr;
            a[g][0] = *(const unsigned*)&sW[r * 200 + kk];
            a[g][1] = *(const unsigned*)&sW[(r + 8) * 200 + kk];
            a[g][2] = *(const unsigned*)&sW[r * 200 + kk + 8];
            a[g][3] = *(const unsigned*)&sW[(r + 8) * 200 + kk + 8];
        }
        unsigned bf[2][2];
        #pragma unroll
        for (int tg = 0; tg < 2; tg++) {
            const __half* xp = sX + (size_t)(tloc + tg * 8) * 200 + kk;
            bf[tg][0] = *(const unsigned*)xp;
            bf[tg][1] = *(const unsigned*)(xp + 8);
        }
        #pragma unroll
        for (int g = 0; g < 3; g++)
            #pragma unroll
            for (int tg = 0; tg < 2; tg++)
                mma16816(acc[g][tg], a[g], bf[tg]);
    }

    #pragma unroll
    for (int g = 0; g < 3; g++) {
        #pragma unroll
        for (int tg = 0; tg < 2; tg++) {
            int T = m0 + w * 16 + tg * 8 + qc;
            #pragma unroll
            for (int q = 0; q < 4; q++) {
                int nb = g * 16 + qr + ((q >= 2) ? 8 : 0);
                int Tt = T + (q & 1);
                float v = acc[g][tg][q];
                if (nb < RNK)        g_dtm[(size_t)Tt * RNK + nb] = v;
                else if (nb < 38)    g_BC[(size_t)Tt * 32 + (nb - RNK)] = v;
            }
        }
    }
}

// ---------------- out_proj via tensor cores ----------------
__global__ void __launch_bounds__(128) outproj_mma(float* __restrict__ out)
{
    __shared__ __half sA[64 * 200];
    const int tid = threadIdx.x;
    const int w = tid >> 5, lane = tid & 31;
    const int m0 = blockIdx.x * 64;
    const int b = m0 >> 12, p0 = m0 & 4095;

    for (int i = tid; i < 64 * 48; i += 128) {
        int m = i / 48, kq = (i - m * 48) * 4;
        float4 yv = *(const float4*)&g_ycomb[(size_t)(m0 + m) * 192 + kq];
        float4 zv = *(const float4*)&g_zs[(size_t)(m0 + m) * 192 + kq];
        *(__half2*)&sA[m * 200 + kq]     = __floats2half2_rn(yv.x * zv.x, yv.y * zv.y);
        *(__half2*)&sA[m * 200 + kq + 2] = __floats2half2_rn(yv.z * zv.z, yv.w * zv.w);
    }
    __syncthreads();

    const int qr = lane >> 2, qc = (lane & 3) << 1;
    const int rA = w * 16 + qr;

    float acc[12][4];
    #pragma unroll
    for (int g = 0; g < 12; g++)
        #pragma unroll
        for (int q = 0; q < 4; q++) acc[g][q] = 0.f;

    for (int ks = 0; ks < 12; ks++) {
        const int k = ks * 16 + qc;
        unsigned a[4];
        a[0] = *(const unsigned*)&sA[rA * 200 + k];
        a[1] = *(const unsigned*)&sA[(rA + 8) * 200 + k];
        a[2] = *(const unsigned*)&sA[rA * 200 + k + 8];
        a[3] = *(const unsigned*)&sA[(rA + 8) * 200 + k + 8];
        #pragma unroll
        for (int g = 0; g < 12; g++) {
            int n = g * 8 + qr;
            unsigned bf[2];
            bf[0] = *(const unsigned*)&g_Wh2[n * 192 + k];
            bf[1] = *(const unsigned*)&g_Wh2[n * 192 + k + 8];
            mma16816(acc[g], a, bf);
        }
    }

    #pragma unroll
    for (int g = 0; g < 12; g++) {
        int nc = g * 8 + qc;
        int t = p0 + w * 16 + qr;
        out[((size_t)b * 96 + nc)     * 4096 + t]     = acc[g][0];
        out[((size_t)b * 96 + nc + 1) * 4096 + t]     = acc[g][1];
        out[((size_t)b * 96 + nc)     * 4096 + t + 8] = acc[g][2];
        out[((size_t)b * 96 + nc + 1) * 4096 + t + 8] = acc[g][3];
    }
}

// ---------------- chunked selective scan (dt_proj + conv fused into staging) ----------------
__global__ void __launch_bounds__(128) scanA_kernel(const float* __restrict__ A_log,
    const float* __restrict__ dtw, const float* __restrict__ dtb,
    const float* __restrict__ cw, const float* __restrict__ cb)
{
    __shared__ float2 sdu[16][CT + 2];
    __shared__ float2 sB[CT][8];
    __shared__ float sdt[RNK][CT + 2];
    __shared__ float swr[16][RNK];
    __shared__ float sbias[16];
    __shared__ __half sXs[67][18];
    __shared__ float scw[16][4];
    __shared__ float scb[16];
    const int tid = threadIdx.x;
    const int c = blockIdx.x, dg = blockIdx.y, n = blockIdx.z;
    const int l0 = c * CT, d0 = dg * 16;
    const int b = n & 3, k = n >> 2;

    {
        const float* src = g_dtm + ((size_t)n * LL + l0) * RNK;
        for (int i = tid; i < CT * RNK; i += 128) {
            int l = i / RNK, r = i - l * RNK;
            sdt[r][l] = src[i];
        }
    }
    if (tid < 16 * RNK) swr[tid / RNK][tid % RNK] = dtw[(d0 + tid / RNK) * RNK + tid % RNK];
    else if (tid >= 96 && tid < 112) sbias[tid - 96] = dtb[d0 + tid - 96];
    if (tid < 64) scw[tid >> 2][tid & 3] = cw[(d0 + (tid >> 2)) * 4 + (tid & 3)];
    else if (tid >= 64 && tid < 80) scb[tid - 64] = cb[d0 + tid - 64];
    for (int i = tid; i < 67 * 8; i += 128) {
        int idx = i >> 3, q = (i & 7) << 1;
        int pix = l0 - 3 + idx;
        __half2 v = (pix >= 0)
            ? *(const __half2*)&g_xsh[((size_t)b * LL + pmap(pix, k)) * DI + d0 + q]
            : __floats2half2_rn(0.f, 0.f);
        *(__half2*)&sXs[idx][q] = v;
    }
    for (int i = tid; i < CT * 8; i += 128) {
        int l = i >> 3, j = i & 7;
        sB[l][j] = *(const float2*)&g_BC[((size_t)n * LL + l0 + l) * 32 + 2 * j];
    }
    __syncthreads();

    for (int i = tid; i < 16 * 32; i += 128) {
        int dd = i >> 5, l2 = (i & 31) << 1;
        float u0 = scb[dd], u1 = scb[dd];
        #pragma unroll
        for (int tap = 0; tap < 4; tap++) {
            float wv = scw[dd][tap];
            u0 += wv * __half2float(sXs[l2 + tap][dd]);
            u1 += wv * __half2float(sXs[l2 + 1 + tap][dd]);
        }
        float s0 = sbias[dd], s1 = s0;
        #pragma unroll
        for (int r = 0; r < RNK; r++) {
            float wv = swr[dd][r];
            s0 += sdt[r][l2] * wv;
            s1 += sdt[r][l2 + 1] * wv;
        }
        sdu[dd][l2]     = make_float2(softplus_f(s0), silu(u0));
        sdu[dd][l2 + 1] = make_float2(softplus_f(s1), silu(u1));
    }
    const int lane = tid & 31, w = tid >> 5;
    const int j = lane & 7, dloc = (w << 2) | (lane >> 3);
    const int d = d0 + dloc;
    float2 al = *(const float2*)&A_log[d * DS + 2 * j];
    const float cA0 = -expf(al.x) * 1.4426950408889634f;
    const float cA1 = -expf(al.y) * 1.4426950408889634f;
    __syncthreads();

    float h0 = 0.f, h1 = 0.f, S = 0.f;
    #pragma unroll 4
    for (int l = 0; l < CT; ++l) {
        float2 du = sdu[dloc][l];
        float2 Bv = sB[l][j];
        float a0 = ex2(du.x * cA0);
        float a1 = ex2(du.x * cA1);
        float du2 = du.x * du.y;
        h0 = a0 * h0 + du2 * Bv.x;
        h1 = a1 * h1 + du2 * Bv.y;
        S += du.x;
    }
    size_t o = ((size_t)(n * NC + c)) * (DI * DS) + d * DS + 2 * j;
    *(float2*)&g_H[o] = make_float2(h0, h1);
    *(float2*)&g_P[o] = make_float2(ex2(cA0 * S), ex2(cA1 * S));
}

__global__ void __launch_bounds__(256) scanB_kernel()
{
    const int gid = blockIdx.x * 256 + threadIdx.x;
    const int n = gid / (DI * DS);
    const int ds = gid - n * (DI * DS);
    size_t base = (size_t)n * NC * (DI * DS) + ds;
    float h = 0.f;
    #pragma unroll 4
    for (int cc = 0; cc < NC; ++cc) {
        size_t a = base + (size_t)cc * (DI * DS);
        float Pv = g_P[a], Hv = g_H[a];
        g_H[a] = h;
        h = Pv * h + Hv;
    }
}

__global__ void __launch_bounds__(128) scanC_kernel(
    const float* __restrict__ A_log, const float* __restrict__ Dp,
    const float* __restrict__ dtw, const float* __restrict__ dtb,
    const float* __restrict__ cw, const float* __restrict__ cb)
{
    __shared__ float2 sdu[16][CT + 2];
    __shared__ float2 sB[CT][8];
    __shared__ float2 sC[CT][8];
    __shared__ float sg[CT];
    __shared__ float sv[CT][16];
    __shared__ int sp[CT];
    __shared__ float sdt[RNK][CT + 2];
    __shared__ float swr[16][RNK];
    __shared__ float sbias[16];
    __shared__ __half sXs[67][18];
    __shared__ float scw[16][4];
    __shared__ float scb[16];
    const int tid = threadIdx.x;
    const int c = blockIdx.x, dg = blockIdx.y, n = blockIdx.z;
    const int l0 = c * CT, d0 = dg * 16;
    const int b = n & 3, k = n >> 2;

    {
        const float* src = g_dtm + ((size_t)n * LL + l0) * RNK;
        for (int i = tid; i < CT * RNK; i += 128) {
            int l = i / RNK, r = i - l * RNK;
            sdt[r][l] = src[i];
        }
    }
    if (tid < 16 * RNK) swr[tid / RNK][tid % RNK] = dtw[(d0 + tid / RNK) * RNK + tid % RNK];
    else if (tid >= 96 && tid < 112) sbias[tid - 96] = dtb[d0 + tid - 96];
    if (tid < 64) scw[tid >> 2][tid & 3] = cw[(d0 + (tid >> 2)) * 4 + (tid & 3)];
    else if (tid >= 64 && tid < 80) scb[tid - 64] = cb[d0 + tid - 64];
    for (int i = tid; i < 67 * 8; i += 128) {
        int idx = i >> 3, q = (i & 7) << 1;
        int pix = l0 - 3 + idx;
        __half2 v = (pix >= 0)
            ? *(const __half2*)&g_xsh[((size_t)b * LL + pmap(pix, k)) * DI + d0 + q]
            : __floats2half2_rn(0.f, 0.f);
        *(__half2*)&sXs[idx][q] = v;
    }
    for (int i = tid; i < CT * 8; i += 128) {
        int l = i >> 3, j = i & 7;
        const float* bc = &g_BC[((size_t)n * LL + l0 + l) * 32];
        sB[l][j] = *(const float2*)(bc + 2 * j);
        sC[l][j] = *(const float2*)(bc + 16 + 2 * j);
    }
    if (tid < CT) {
        sp[tid] = pmap(l0 + tid, k);
        sg[tid] = g_gateT[(size_t)n * LL + l0 + tid];
    }
    __syncthreads();

    for (int i = tid; i < 16 * 32; i += 128) {
        int dd = i >> 5, l2 = (i & 31) << 1;
        float u0 = scb[dd], u1 = scb[dd];
        #pragma unroll
        for (int tap = 0; tap < 4; tap++) {
            float wv = scw[dd][tap];
            u0 += wv * __half2float(sXs[l2 + tap][dd]);
            u1 += wv * __half2float(sXs[l2 + 1 + tap][dd]);
        }
        float s0 = sbias[dd], s1 = s0;
        #pragma unroll
        for (int r = 0; r < RNK; r++) {
            float wv = swr[dd][r];
            s0 += sdt[r][l2] * wv;
            s1 += sdt[r][l2 + 1] * wv;
        }
        sdu[dd][l2]     = make_float2(softplus_f(s0), silu(u0));
        sdu[dd][l2 + 1] = make_float2(softplus_f(s1), silu(u1));
    }
    const int lane = tid & 31, w = tid >> 5;
    const int j = lane & 7, dloc = (w << 2) | (lane >> 3);
    const int d = d0 + dloc;
    float2 al = *(const float2*)&A_log[d * DS + 2 * j];
    const float cA0 = -expf(al.x) * 1.4426950408889634f;
    const float cA1 = -expf(al.y) * 1.4426950408889634f;
    const float Dd = Dp[d];
    __syncthreads();

    float2 hv = *(const float2*)&g_H[((size_t)(n * NC + c)) * (DI * DS) + d * DS + 2 * j];
    float h0 = hv.x, h1 = hv.y;

    #pragma unroll 4
    for (int l = 0; l < CT; ++l) {
        float2 du = sdu[dloc][l];
        float2 Bv = sB[l][j];
        float2 Cv = sC[l][j];
        float a0 = ex2(du.x * cA0);
        float a1 = ex2(du.x * cA1);
        float du2 = du.x * du.y;
        h0 = a0 * h0 + du2 * Bv.x;
        h1 = a1 * h1 + du2 * Bv.y;
        float y = h0 * Cv.x + h1 * Cv.y;
        y += __shfl_xor_sync(0xffffffffu, y, 1);
        y += __shfl_xor_sync(0xffffffffu, y, 2);
        y += __shfl_xor_sync(0xffffffffu, y, 4);
        if (j == 0)
            sv[l][dloc] = (y + du.y * Dd) * sg[l];
    }
    __syncthreads();

    float* ycb = g_ycomb + (size_t)b * LL * DI + d0;
    #pragma unroll
    for (int jj = 0; jj < 8; jj++) {
        int i = tid + jj * 128;
        int dd = i & 15, l = i >> 4;
        atomicAdd(ycb + (size_t)sp[l] * DI + dd, sv[l][dd]);
    }
}

// ---------------- launch ----------------
extern "C" void kernel_launch(void* const* d_in, const int* in_sizes, int n_in,
                              void* d_out, int out_size)
{
    const float* x         = (const float*)d_in[0];
    const float* norm_g    = (const float*)d_in[1];
    const float* norm_b    = (const float*)d_in[2];
    const float* gate_w1   = (const float*)d_in[3];
    const float* gate_b1   = (const float*)d_in[4];
    const float* gate_w2   = (const float*)d_in[5];
    const float* gate_b2   = (const float*)d_in[6];
    const float* in_proj_w = (const float*)d_in[7];
    const float* conv_w    = (const float*)d_in[8];
    const float* conv_b    = (const float*)d_in[9];
    const float* x_proj_w  = (const float*)d_in[10];
    const float* dt_proj_w = (const float*)d_in[11];
    const float* dt_proj_b = (const float*)d_in[12];
    const float* A_log     = (const float*)d_in[13];
    const float* Dvec      = (const float*)d_in[14];
    const float* out_proj_w= (const float*)d_in[15];
    float* out = (float*)d_out;

    cudaFuncSetAttribute(xproj_mma, cudaFuncAttributeMaxDynamicSharedMemorySize, 73728);

    norm_gate_kernel<<<512, 128>>>(x, norm_g, norm_b, gate_w1, gate_b1, gate_w2, gate_b2,
                                   x_proj_w, out_proj_w, in_proj_w);
    inproj_mma<<<256, 256>>>();
    xproj_mma<<<1024, 128, 71600>>>(conv_w, conv_b);
    scanA_kernel<<<dim3(NC, 12, NDIR), 128>>>(A_log, dt_proj_w, dt_proj_b, conv_w, conv_b);
    scanB_kernel<<<(NDIR * DI * DS) / 256, 256>>>();
    scanC_kernel<<<dim3(NC, 12, NDIR), 128>>>(A_log, Dvec, dt_proj_w, dt_proj_b, conv_w, conv_b);
    outproj_mma<<<256, 128>>>(out);
}